// round 1
// baseline (speedup 1.0000x reference)
#include <cuda_runtime.h>
#include <math.h>

// ---------------- problem constants ----------------
#define LL_ 4
#define B_  2
#define N_  4096
#define D_  1024
#define H_  16
#define HD_ 64
#define KP_ 256
#define FF_ 4096

#define BND_  (B_*N_*D_)          // 8388608
#define KPD_  (B_*KP_*D_)         // 524288
#define SCO_  (B_*H_*N_*KP_)      // 33554432
#define HBF_  (B_*N_*FF_)         // 33554432
#define SPLITK_ 8

// scratch layout (floats)
#define OFF_Q   ((size_t)0)
#define OFF_K   ((size_t)BND_)
#define OFF_V   ((size_t)2*BND_)
#define OFF_KP  ((size_t)3*BND_)
#define OFF_VP  (OFF_KP + KPD_)
#define OFF_SC  (OFF_VP + KPD_)
#define OFF_T1  (OFF_SC + SCO_)
#define OFF_Y   (OFF_T1 + BND_)
#define OFF_HB  (OFF_Y  + BND_)
#define OFF_XB  (OFF_HB + HBF_)
#define OFF_KPP (OFF_XB + BND_)
#define OFF_VPP (OFF_KPP + (size_t)SPLITK_*KPD_)
#define SCRATCH_FLOATS (OFF_VPP + (size_t)SPLITK_*KPD_)

__device__ float g_scratch[SCRATCH_FLOATS];

// ---------------- helpers ----------------
__device__ __forceinline__ float tf32r(float x) {
    unsigned u;
    asm("cvt.rna.tf32.f32 %0, %1;" : "=r"(u) : "f"(x));
    return __uint_as_float(u);
}

__device__ __forceinline__ float gelu_exact(float x) {
    return 0.5f * x * (1.0f + erff(x * 0.70710678118654752f));
}

__device__ __forceinline__ void mma_tf32(float c[4], const unsigned a[4], const unsigned b[2]) {
    asm volatile(
        "mma.sync.aligned.m16n8k8.row.col.f32.tf32.tf32.f32 "
        "{%0,%1,%2,%3}, {%4,%5,%6,%7}, {%8,%9}, {%0,%1,%2,%3};"
        : "+f"(c[0]), "+f"(c[1]), "+f"(c[2]), "+f"(c[3])
        : "r"(a[0]), "r"(a[1]), "r"(a[2]), "r"(a[3]),
          "r"(b[0]), "r"(b[1]));
}

// ---------------- generic tf32 tensor-core GEMM ----------------
// C(M,N) = A(M,K) * B(K,N)  [+ bias[col]] [gelu]
// TA: A stored K-major (K x M);  TB: B stored N x K (row n has K contiguous)
// batching: z -> (zk splitK slice, zi inner batch, zo outer batch)
template<int BM, int BN, int BK, int WM, int WN, bool TA, bool TB, int EPI>
__global__ void __launch_bounds__((BM/WM)*(BN/WN)*32)
gemm_tc(const float* __restrict__ Ag, const float* __restrict__ Bg,
        float* __restrict__ Cg, const float* __restrict__ bias,
        int M, int N, int Kd, int lda, int ldb, int ldc,
        long long sAi, long long sAo, long long sBi, long long sBo,
        long long sCi, long long sCo, long long sCk,
        int binner, int splitK)
{
    constexpr int NWARP   = (BM/WM)*(BN/WN);
    constexpr int THREADS = NWARP*32;
    __shared__ float As[BK][BM+4];
    __shared__ float Bs[BK][BN+4];

    const int z  = blockIdx.z;
    const int zk = z % splitK;
    const int zb = z / splitK;
    const int zi = zb % binner;
    const int zo = zb / binner;
    const float* A = Ag + zi*sAi + zo*sAo;
    const float* B = Bg + zi*sBi + zo*sBo;
    float*       C = Cg + zi*sCi + zo*sCo + (long long)zk*sCk;

    const int m0 = blockIdx.y * BM;
    const int n0 = blockIdx.x * BN;
    const int kPer = Kd / splitK;
    const int kbeg = zk * kPer;
    const int kend = kbeg + kPer;

    const int tid  = threadIdx.x;
    const int w    = tid >> 5;
    const int lane = tid & 31;
    constexpr int WGM = BM/WM;
    const int wmB = (w % WGM) * WM;
    const int wnB = (w / WGM) * WN;
    const int lr = lane >> 2;
    const int lc = lane & 3;

    constexpr int MT  = WM/16;
    constexpr int NTN = WN/8;
    float acc[MT][NTN][4];
#pragma unroll
    for (int i = 0; i < MT; i++)
#pragma unroll
        for (int j = 0; j < NTN; j++)
#pragma unroll
            for (int q2 = 0; q2 < 4; q2++) acc[i][j][q2] = 0.f;

    for (int kb = kbeg; kb < kend; kb += BK) {
        // ---- stage A tile into As[k][m] (tf32-rounded) ----
        if constexpr (!TA) {
            constexpr int NK4  = BK/4;
            constexpr int TRIP = (BM*NK4)/THREADS;
#pragma unroll
            for (int t = 0; t < TRIP; t++) {
                int i  = tid + t*THREADS;
                int m  = i / NK4;
                int k4 = (i - m*NK4) * 4;
                float4 vv = *reinterpret_cast<const float4*>(A + (size_t)(m0+m)*lda + kb + k4);
                As[k4+0][m] = tf32r(vv.x);
                As[k4+1][m] = tf32r(vv.y);
                As[k4+2][m] = tf32r(vv.z);
                As[k4+3][m] = tf32r(vv.w);
            }
        } else {
            constexpr int NM4  = BM/4;
            constexpr int TRIP = (BK*NM4)/THREADS;
#pragma unroll
            for (int t = 0; t < TRIP; t++) {
                int i  = tid + t*THREADS;
                int kq = i / NM4;
                int m4 = (i - kq*NM4) * 4;
                float4 vv = *reinterpret_cast<const float4*>(A + (size_t)(kb+kq)*lda + m0 + m4);
                vv.x = tf32r(vv.x); vv.y = tf32r(vv.y);
                vv.z = tf32r(vv.z); vv.w = tf32r(vv.w);
                *reinterpret_cast<float4*>(&As[kq][m4]) = vv;
            }
        }
        // ---- stage B tile into Bs[k][n] ----
        if constexpr (!TB) {
            constexpr int NN4  = BN/4;
            constexpr int TRIP = (BK*NN4)/THREADS;
#pragma unroll
            for (int t = 0; t < TRIP; t++) {
                int i  = tid + t*THREADS;
                int kq = i / NN4;
                int n4 = (i - kq*NN4) * 4;
                float4 vv = *reinterpret_cast<const float4*>(B + (size_t)(kb+kq)*ldb + n0 + n4);
                vv.x = tf32r(vv.x); vv.y = tf32r(vv.y);
                vv.z = tf32r(vv.z); vv.w = tf32r(vv.w);
                *reinterpret_cast<float4*>(&Bs[kq][n4]) = vv;
            }
        } else {
            constexpr int NK4  = BK/4;
            constexpr int TRIP = (BN*NK4)/THREADS;
#pragma unroll
            for (int t = 0; t < TRIP; t++) {
                int i  = tid + t*THREADS;
                int n  = i / NK4;
                int k4 = (i - n*NK4) * 4;
                float4 vv = *reinterpret_cast<const float4*>(B + (size_t)(n0+n)*ldb + kb + k4);
                Bs[k4+0][n] = tf32r(vv.x);
                Bs[k4+1][n] = tf32r(vv.y);
                Bs[k4+2][n] = tf32r(vv.z);
                Bs[k4+3][n] = tf32r(vv.w);
            }
        }
        __syncthreads();

        // ---- compute ----
#pragma unroll
        for (int kk = 0; kk < BK; kk += 8) {
            unsigned af[MT][4], bfv[NTN][2];
#pragma unroll
            for (int mt = 0; mt < MT; mt++) {
                af[mt][0] = __float_as_uint(As[kk+lc  ][wmB+mt*16+lr  ]);
                af[mt][1] = __float_as_uint(As[kk+lc  ][wmB+mt*16+lr+8]);
                af[mt][2] = __float_as_uint(As[kk+lc+4][wmB+mt*16+lr  ]);
                af[mt][3] = __float_as_uint(As[kk+lc+4][wmB+mt*16+lr+8]);
            }
#pragma unroll
            for (int nt = 0; nt < NTN; nt++) {
                bfv[nt][0] = __float_as_uint(Bs[kk+lc  ][wnB+nt*8+lr]);
                bfv[nt][1] = __float_as_uint(Bs[kk+lc+4][wnB+nt*8+lr]);
            }
#pragma unroll
            for (int mt = 0; mt < MT; mt++)
#pragma unroll
                for (int nt = 0; nt < NTN; nt++)
                    mma_tf32(acc[mt][nt], af[mt], bfv[nt]);
        }
        __syncthreads();
    }

    // ---- epilogue ----
#pragma unroll
    for (int mt = 0; mt < MT; mt++) {
#pragma unroll
        for (int nt = 0; nt < NTN; nt++) {
            int r = m0 + wmB + mt*16 + lr;
            int c = n0 + wnB + nt*8 + lc*2;
            float v0 = acc[mt][nt][0], v1 = acc[mt][nt][1];
            float v2 = acc[mt][nt][2], v3 = acc[mt][nt][3];
            if constexpr (EPI >= 1) {
                float bc0 = bias[c], bc1 = bias[c+1];
                v0 += bc0; v1 += bc1; v2 += bc0; v3 += bc1;
            }
            if constexpr (EPI == 2) {
                v0 = gelu_exact(v0); v1 = gelu_exact(v1);
                v2 = gelu_exact(v2); v3 = gelu_exact(v3);
            }
            *reinterpret_cast<float2*>(C + (size_t)r*ldc + c)     = make_float2(v0, v1);
            *reinterpret_cast<float2*>(C + (size_t)(r+8)*ldc + c) = make_float2(v2, v3);
        }
    }
}

// ---------------- split-K reduce (deterministic, no atomics) ----------------
__global__ void reduce_slices(const float* __restrict__ part, float* __restrict__ out,
                              int n, int slices, long long stride)
{
    int i = blockIdx.x * blockDim.x + threadIdx.x;
    if (i < n) {
        float s = 0.f;
        for (int t = 0; t < slices; t++) s += part[i + (long long)t*stride];
        out[i] = s;
    }
}

// ---------------- softmax over rows of 256 (scale 1/sqrt(64) folded in) -----
__global__ void softmax256(float* __restrict__ S, int nrows)
{
    int row = blockIdx.x * 8 + (threadIdx.x >> 5);
    if (row >= nrows) return;
    int lane = threadIdx.x & 31;
    float* p = S + (size_t)row * 256;
    float4 a = *reinterpret_cast<float4*>(p + lane*4);
    float4 b = *reinterpret_cast<float4*>(p + 128 + lane*4);
    const float sc = 0.125f;
    a.x *= sc; a.y *= sc; a.z *= sc; a.w *= sc;
    b.x *= sc; b.y *= sc; b.z *= sc; b.w *= sc;
    float m = fmaxf(fmaxf(fmaxf(a.x, a.y), fmaxf(a.z, a.w)),
                    fmaxf(fmaxf(b.x, b.y), fmaxf(b.z, b.w)));
#pragma unroll
    for (int o = 16; o; o >>= 1) m = fmaxf(m, __shfl_xor_sync(0xffffffffu, m, o));
    a.x = expf(a.x - m); a.y = expf(a.y - m); a.z = expf(a.z - m); a.w = expf(a.w - m);
    b.x = expf(b.x - m); b.y = expf(b.y - m); b.z = expf(b.z - m); b.w = expf(b.w - m);
    float s = a.x + a.y + a.z + a.w + b.x + b.y + b.z + b.w;
#pragma unroll
    for (int o = 16; o; o >>= 1) s += __shfl_xor_sync(0xffffffffu, s, o);
    float r = 1.0f / s;
    a.x *= r; a.y *= r; a.z *= r; a.w *= r;
    b.x *= r; b.y *= r; b.z *= r; b.w *= r;
    *reinterpret_cast<float4*>(p + lane*4)       = a;
    *reinterpret_cast<float4*>(p + 128 + lane*4) = b;
}

// ---------------- residual add + LayerNorm over D=1024 ----------------
__device__ __forceinline__ float block_sum_256(float v, float* sh)
{
#pragma unroll
    for (int o = 16; o; o >>= 1) v += __shfl_xor_sync(0xffffffffu, v, o);
    int w = threadIdx.x >> 5, lane = threadIdx.x & 31;
    if (lane == 0) sh[w] = v;
    __syncthreads();
    if (w == 0) {
        float t = (lane < 8) ? sh[lane] : 0.f;
#pragma unroll
        for (int o = 4; o; o >>= 1) t += __shfl_xor_sync(0xffffffffu, t, o);
        if (lane == 0) sh[0] = t;
    }
    __syncthreads();
    float r = sh[0];
    __syncthreads();
    return r;
}

__global__ void add_ln(const float* __restrict__ xa, const float* __restrict__ xb,
                       const float* __restrict__ g, const float* __restrict__ bt,
                       float* __restrict__ out)
{
    __shared__ float sh[8];
    int row = blockIdx.x;
    int tid = threadIdx.x;          // 256 threads, 4 elems each
    size_t base = (size_t)row * D_;
    float4 v = reinterpret_cast<const float4*>(xa + base)[tid];
    float4 r = reinterpret_cast<const float4*>(xb + base)[tid];
    v.x += r.x; v.y += r.y; v.z += r.z; v.w += r.w;
    float s = v.x + v.y + v.z + v.w;
    float mean = block_sum_256(s, sh) * (1.0f / D_);
    float d0 = v.x - mean, d1 = v.y - mean, d2 = v.z - mean, d3 = v.w - mean;
    float sq = d0*d0 + d1*d1 + d2*d2 + d3*d3;
    float var = block_sum_256(sq, sh) * (1.0f / D_);
    float rs = rsqrtf(var + 1e-12f);
    float4 gg = reinterpret_cast<const float4*>(g)[tid];
    float4 bb = reinterpret_cast<const float4*>(bt)[tid];
    float4 o;
    o.x = d0 * rs * gg.x + bb.x;
    o.y = d1 * rs * gg.y + bb.y;
    o.z = d2 * rs * gg.z + bb.z;
    o.w = d3 * rs * gg.w + bb.w;
    reinterpret_cast<float4*>(out + base)[tid] = o;
}

// ---------------- orchestration ----------------
extern "C" void kernel_launch(void* const* d_in, const int* in_sizes, int n_in,
                              void* d_out, int out_size)
{
    (void)in_sizes; (void)n_in; (void)out_size;
    const float* x   = (const float*)d_in[0];
    const float* Wq  = (const float*)d_in[1];
    const float* Wk  = (const float*)d_in[2];
    const float* Wv  = (const float*)d_in[3];
    const float* E   = (const float*)d_in[4];
    const float* F   = (const float*)d_in[5];
    const float* g1  = (const float*)d_in[6];
    const float* bl1 = (const float*)d_in[7];
    const float* W1  = (const float*)d_in[8];
    const float* bb1 = (const float*)d_in[9];
    const float* W2  = (const float*)d_in[10];
    const float* bb2 = (const float*)d_in[11];
    const float* g2  = (const float*)d_in[12];
    const float* bl2 = (const float*)d_in[13];
    float* out = (float*)d_out;

    float* S = nullptr;
    cudaGetSymbolAddress((void**)&S, g_scratch);
    float* qb  = S + OFF_Q;
    float* kb  = S + OFF_K;
    float* vb  = S + OFF_V;
    float* kp  = S + OFF_KP;
    float* vp  = S + OFF_VP;
    float* sc  = S + OFF_SC;
    float* t1  = S + OFF_T1;
    float* yb  = S + OFF_Y;
    float* hb  = S + OFF_HB;
    float* xb  = S + OFF_XB;
    float* kpp = S + OFF_KPP;
    float* vpp = S + OFF_VPP;

    const long long NDll  = (long long)N_ * D_;
    const long long KPDll = (long long)KP_ * D_;
    const long long NKPll = (long long)N_ * KP_;

    for (int l = 0; l < LL_; l++) {
        const float* xin = (l == 0) ? x : xb;

        // --- Q, K, V projections: [8192,1024] x [1024,1024], NN ---
        dim3 gQ(D_/128, (B_*N_)/128, 1);
        gemm_tc<128,128,32,32,64,false,false,0><<<gQ,256>>>(
            xin, Wq + (size_t)l*D_*D_, qb, nullptr,
            B_*N_, D_, D_, D_, D_, D_, 0,0,0,0,0,0,0, 1, 1);
        gemm_tc<128,128,32,32,64,false,false,0><<<gQ,256>>>(
            xin, Wk + (size_t)l*D_*D_, kb, nullptr,
            B_*N_, D_, D_, D_, D_, D_, 0,0,0,0,0,0,0, 1, 1);
        gemm_tc<128,128,32,32,64,false,false,0><<<gQ,256>>>(
            xin, Wv + (size_t)l*D_*D_, vb, nullptr,
            B_*N_, D_, D_, D_, D_, D_, 0,0,0,0,0,0,0, 1, 1);

        // --- kp = E^T k, vp = F^T v : [256,1024], K=4096, TN, split-K=8 ---
        dim3 gP(D_/64, KP_/64, B_*SPLITK_);
        gemm_tc<64,64,32,32,32,true,false,0><<<gP,128>>>(
            E + (size_t)l*N_*KP_, kb, kpp, nullptr,
            KP_, D_, N_, KP_, D_, D_,
            0,0, 0,NDll, 0,KPDll, (long long)KPD_, 1, SPLITK_);
        gemm_tc<64,64,32,32,32,true,false,0><<<gP,128>>>(
            F + (size_t)l*N_*KP_, vb, vpp, nullptr,
            KP_, D_, N_, KP_, D_, D_,
            0,0, 0,NDll, 0,KPDll, (long long)KPD_, 1, SPLITK_);
        reduce_slices<<<KPD_/256,256>>>(kpp, kp, KPD_, SPLITK_, (long long)KPD_);
        reduce_slices<<<KPD_/256,256>>>(vpp, vp, KPD_, SPLITK_, (long long)KPD_);

        // --- scores[b,h] = Q_h Kp_h^T : [4096,256], K=64, NT, batched b*h ---
        dim3 gS(KP_/128, N_/128, B_*H_);
        gemm_tc<128,128,32,32,64,false,true,0><<<gS,256>>>(
            qb, kp, sc, nullptr,
            N_, KP_, HD_, D_, D_, KP_,
            HD_, NDll, HD_, KPDll, NKPll, (long long)H_*NKPll, 0, H_, 1);

        // --- softmax (in place, scale 1/8 folded in) ---
        softmax256<<<(B_*H_*N_)/8,256>>>(sc, B_*H_*N_);

        // --- attn = P Vp_h : [4096,64], K=256, NN, batched ---
        dim3 gA(HD_/64, N_/128, B_*H_);
        gemm_tc<128,64,32,32,32,false,false,0><<<gA,256>>>(
            sc, vp, t1, nullptr,
            N_, HD_, KP_, KP_, D_, D_,
            NKPll, (long long)H_*NKPll, HD_, KPDll, HD_, NDll, 0, H_, 1);

        // --- y = LN(attn + x) ---
        add_ln<<<B_*N_,256>>>(t1, xin, g1 + (size_t)l*D_, bl1 + (size_t)l*D_, yb);

        // --- h = gelu(y W1^T + b1) : [8192,4096], K=1024, NT ---
        dim3 gF1(FF_/128, (B_*N_)/128, 1);
        gemm_tc<128,128,32,32,64,false,true,2><<<gF1,256>>>(
            yb, W1 + (size_t)l*FF_*D_, hb, bb1 + (size_t)l*FF_,
            B_*N_, FF_, D_, D_, D_, FF_, 0,0,0,0,0,0,0, 1, 1);

        // --- o = h W2^T + b2 : [8192,1024], K=4096, NT ---
        dim3 gF2(D_/128, (B_*N_)/128, 1);
        gemm_tc<128,128,32,32,64,false,true,1><<<gF2,256>>>(
            hb, W2 + (size_t)l*D_*FF_, t1, bb2 + (size_t)l*D_,
            B_*N_, D_, FF_, FF_, FF_, D_, 0,0,0,0,0,0,0, 1, 1);

        // --- x_next = LN(o + y) ---
        add_ln<<<B_*N_,256>>>(t1, yb, g2 + (size_t)l*D_, bl2 + (size_t)l*D_,
                              (l == LL_-1) ? out : xb);
    }
}

// round 2
// speedup vs baseline: 1.0020x; 1.0020x over previous
#include <cuda_runtime.h>
#include <math.h>

// ---------------- problem constants ----------------
#define LL_ 4
#define B_  2
#define N_  4096
#define D_  1024
#define H_  16
#define HD_ 64
#define KP_ 256
#define FF_ 4096

#define BND_  (B_*N_*D_)          // 8388608
#define KPD_  (B_*KP_*D_)         // 524288
#define SCO_  (B_*H_*N_*KP_)      // 33554432
#define HBF_  (B_*N_*FF_)         // 33554432
#define SPLITK_ 8

// scratch layout (floats)
#define OFF_Q   ((size_t)0)
#define OFF_K   ((size_t)BND_)
#define OFF_V   ((size_t)2*BND_)
#define OFF_KP  ((size_t)3*BND_)
#define OFF_VP  (OFF_KP + KPD_)
#define OFF_SC  (OFF_VP + KPD_)
#define OFF_T1  (OFF_SC + SCO_)
#define OFF_Y   (OFF_T1 + BND_)
#define OFF_HB  (OFF_Y  + BND_)
#define OFF_XB  (OFF_HB + HBF_)
#define OFF_KPP (OFF_XB + BND_)
#define OFF_VPP (OFF_KPP + (size_t)SPLITK_*KPD_)
#define SCRATCH_FLOATS (OFF_VPP + (size_t)SPLITK_*KPD_)

__device__ float g_scratch[SCRATCH_FLOATS];

// ---------------- helpers ----------------
__device__ __forceinline__ float tf32r(float x) {
    unsigned u;
    asm("cvt.rna.tf32.f32 %0, %1;" : "=r"(u) : "f"(x));
    return __uint_as_float(u);
}

__device__ __forceinline__ float gelu_exact(float x) {
    return 0.5f * x * (1.0f + erff(x * 0.70710678118654752f));
}

__device__ __forceinline__ void mma_tf32(float c[4], const unsigned a[4], const unsigned b[2]) {
    asm volatile(
        "mma.sync.aligned.m16n8k8.row.col.f32.tf32.tf32.f32 "
        "{%0,%1,%2,%3}, {%4,%5,%6,%7}, {%8,%9}, {%0,%1,%2,%3};"
        : "+f"(c[0]), "+f"(c[1]), "+f"(c[2]), "+f"(c[3])
        : "r"(a[0]), "r"(a[1]), "r"(a[2]), "r"(a[3]),
          "r"(b[0]), "r"(b[1]));
}

// ---------------- generic tf32 tensor-core GEMM ----------------
// C(M,N) = A(M,K) * B(K,N)  [+ bias[col]] [gelu]
// TA: A stored K-major (K x M);  TB: B stored N x K (row n has K contiguous)
// batching: z -> (zk splitK slice, zi inner batch, zo outer batch)
template<int BM, int BN, int BK, int WM, int WN, bool TA, bool TB, int EPI>
__global__ void __launch_bounds__((BM/WM)*(BN/WN)*32)
gemm_tc(const float* __restrict__ Ag, const float* __restrict__ Bg,
        float* __restrict__ Cg, const float* __restrict__ bias,
        int M, int N, int Kd, int lda, int ldb, int ldc,
        long long sAi, long long sAo, long long sBi, long long sBo,
        long long sCi, long long sCo, long long sCk,
        int binner, int splitK)
{
    constexpr int NWARP   = (BM/WM)*(BN/WN);
    constexpr int THREADS = NWARP*32;
    __shared__ float As[BK][BM+4];
    __shared__ float Bs[BK][BN+4];

    const int z  = blockIdx.z;
    const int zk = z % splitK;
    const int zb = z / splitK;
    const int zi = zb % binner;
    const int zo = zb / binner;
    const float* A = Ag + zi*sAi + zo*sAo;
    const float* B = Bg + zi*sBi + zo*sBo;
    float*       C = Cg + zi*sCi + zo*sCo + (long long)zk*sCk;

    const int m0 = blockIdx.y * BM;
    const int n0 = blockIdx.x * BN;
    const int kPer = Kd / splitK;
    const int kbeg = zk * kPer;
    const int kend = kbeg + kPer;

    const int tid  = threadIdx.x;
    const int w    = tid >> 5;
    const int lane = tid & 31;
    constexpr int WGM = BM/WM;
    const int wmB = (w % WGM) * WM;
    const int wnB = (w / WGM) * WN;
    const int lr = lane >> 2;
    const int lc = lane & 3;

    constexpr int MT  = WM/16;
    constexpr int NTN = WN/8;
    float acc[MT][NTN][4];
#pragma unroll
    for (int i = 0; i < MT; i++)
#pragma unroll
        for (int j = 0; j < NTN; j++)
#pragma unroll
            for (int q2 = 0; q2 < 4; q2++) acc[i][j][q2] = 0.f;

    for (int kb = kbeg; kb < kend; kb += BK) {
        // ---- stage A tile into As[k][m] (tf32-rounded) ----
        if constexpr (!TA) {
            constexpr int NK4  = BK/4;
            constexpr int TRIP = (BM*NK4)/THREADS;
#pragma unroll
            for (int t = 0; t < TRIP; t++) {
                int i  = tid + t*THREADS;
                int m  = i / NK4;
                int k4 = (i - m*NK4) * 4;
                float4 vv = *reinterpret_cast<const float4*>(A + (size_t)(m0+m)*lda + kb + k4);
                As[k4+0][m] = tf32r(vv.x);
                As[k4+1][m] = tf32r(vv.y);
                As[k4+2][m] = tf32r(vv.z);
                As[k4+3][m] = tf32r(vv.w);
            }
        } else {
            constexpr int NM4  = BM/4;
            constexpr int TRIP = (BK*NM4)/THREADS;
#pragma unroll
            for (int t = 0; t < TRIP; t++) {
                int i  = tid + t*THREADS;
                int kq = i / NM4;
                int m4 = (i - kq*NM4) * 4;
                float4 vv = *reinterpret_cast<const float4*>(A + (size_t)(kb+kq)*lda + m0 + m4);
                vv.x = tf32r(vv.x); vv.y = tf32r(vv.y);
                vv.z = tf32r(vv.z); vv.w = tf32r(vv.w);
                *reinterpret_cast<float4*>(&As[kq][m4]) = vv;
            }
        }
        // ---- stage B tile into Bs[k][n] ----
        if constexpr (!TB) {
            constexpr int NN4  = BN/4;
            constexpr int TRIP = (BK*NN4)/THREADS;
#pragma unroll
            for (int t = 0; t < TRIP; t++) {
                int i  = tid + t*THREADS;
                int kq = i / NN4;
                int n4 = (i - kq*NN4) * 4;
                float4 vv = *reinterpret_cast<const float4*>(B + (size_t)(kb+kq)*ldb + n0 + n4);
                vv.x = tf32r(vv.x); vv.y = tf32r(vv.y);
                vv.z = tf32r(vv.z); vv.w = tf32r(vv.w);
                *reinterpret_cast<float4*>(&Bs[kq][n4]) = vv;
            }
        } else {
            constexpr int NK4  = BK/4;
            constexpr int TRIP = (BN*NK4)/THREADS;
#pragma unroll
            for (int t = 0; t < TRIP; t++) {
                int i  = tid + t*THREADS;
                int n  = i / NK4;
                int k4 = (i - n*NK4) * 4;
                float4 vv = *reinterpret_cast<const float4*>(B + (size_t)(n0+n)*ldb + kb + k4);
                Bs[k4+0][n] = tf32r(vv.x);
                Bs[k4+1][n] = tf32r(vv.y);
                Bs[k4+2][n] = tf32r(vv.z);
                Bs[k4+3][n] = tf32r(vv.w);
            }
        }
        __syncthreads();

        // ---- compute ----
#pragma unroll
        for (int kk = 0; kk < BK; kk += 8) {
            unsigned af[MT][4], bfv[NTN][2];
#pragma unroll
            for (int mt = 0; mt < MT; mt++) {
                af[mt][0] = __float_as_uint(As[kk+lc  ][wmB+mt*16+lr  ]);
                af[mt][1] = __float_as_uint(As[kk+lc  ][wmB+mt*16+lr+8]);
                af[mt][2] = __float_as_uint(As[kk+lc+4][wmB+mt*16+lr  ]);
                af[mt][3] = __float_as_uint(As[kk+lc+4][wmB+mt*16+lr+8]);
            }
#pragma unroll
            for (int nt = 0; nt < NTN; nt++) {
                bfv[nt][0] = __float_as_uint(Bs[kk+lc  ][wnB+nt*8+lr]);
                bfv[nt][1] = __float_as_uint(Bs[kk+lc+4][wnB+nt*8+lr]);
            }
#pragma unroll
            for (int mt = 0; mt < MT; mt++)
#pragma unroll
                for (int nt = 0; nt < NTN; nt++)
                    mma_tf32(acc[mt][nt], af[mt], bfv[nt]);
        }
        __syncthreads();
    }

    // ---- epilogue ----
#pragma unroll
    for (int mt = 0; mt < MT; mt++) {
#pragma unroll
        for (int nt = 0; nt < NTN; nt++) {
            int r = m0 + wmB + mt*16 + lr;
            int c = n0 + wnB + nt*8 + lc*2;
            float v0 = acc[mt][nt][0], v1 = acc[mt][nt][1];
            float v2 = acc[mt][nt][2], v3 = acc[mt][nt][3];
            if constexpr (EPI >= 1) {
                float bc0 = bias[c], bc1 = bias[c+1];
                v0 += bc0; v1 += bc1; v2 += bc0; v3 += bc1;
            }
            if constexpr (EPI == 2) {
                v0 = gelu_exact(v0); v1 = gelu_exact(v1);
                v2 = gelu_exact(v2); v3 = gelu_exact(v3);
            }
            *reinterpret_cast<float2*>(C + (size_t)r*ldc + c)     = make_float2(v0, v1);
            *reinterpret_cast<float2*>(C + (size_t)(r+8)*ldc + c) = make_float2(v2, v3);
        }
    }
}

// ---------------- split-K reduce (deterministic, no atomics) ----------------
__global__ void reduce_slices(const float* __restrict__ part, float* __restrict__ out,
                              int n, int slices, long long stride)
{
    int i = blockIdx.x * blockDim.x + threadIdx.x;
    if (i < n) {
        float s = 0.f;
        for (int t = 0; t < slices; t++) s += part[i + (long long)t*stride];
        out[i] = s;
    }
}

// ---------------- softmax over rows of 256 (scale 1/sqrt(64) folded in) -----
__global__ void softmax256(float* __restrict__ S, int nrows)
{
    int row = blockIdx.x * 8 + (threadIdx.x >> 5);
    if (row >= nrows) return;
    int lane = threadIdx.x & 31;
    float* p = S + (size_t)row * 256;
    float4 a = *reinterpret_cast<float4*>(p + lane*4);
    float4 b = *reinterpret_cast<float4*>(p + 128 + lane*4);
    const float sc = 0.125f;
    a.x *= sc; a.y *= sc; a.z *= sc; a.w *= sc;
    b.x *= sc; b.y *= sc; b.z *= sc; b.w *= sc;
    float m = fmaxf(fmaxf(fmaxf(a.x, a.y), fmaxf(a.z, a.w)),
                    fmaxf(fmaxf(b.x, b.y), fmaxf(b.z, b.w)));
#pragma unroll
    for (int o = 16; o; o >>= 1) m = fmaxf(m, __shfl_xor_sync(0xffffffffu, m, o));
    a.x = expf(a.x - m); a.y = expf(a.y - m); a.z = expf(a.z - m); a.w = expf(a.w - m);
    b.x = expf(b.x - m); b.y = expf(b.y - m); b.z = expf(b.z - m); b.w = expf(b.w - m);
    float s = a.x + a.y + a.z + a.w + b.x + b.y + b.z + b.w;
#pragma unroll
    for (int o = 16; o; o >>= 1) s += __shfl_xor_sync(0xffffffffu, s, o);
    float r = 1.0f / s;
    a.x *= r; a.y *= r; a.z *= r; a.w *= r;
    b.x *= r; b.y *= r; b.z *= r; b.w *= r;
    *reinterpret_cast<float4*>(p + lane*4)       = a;
    *reinterpret_cast<float4*>(p + 128 + lane*4) = b;
}

// ---------------- residual add + LayerNorm over D=1024 ----------------
__device__ __forceinline__ float block_sum_256(float v, float* sh)
{
#pragma unroll
    for (int o = 16; o; o >>= 1) v += __shfl_xor_sync(0xffffffffu, v, o);
    int w = threadIdx.x >> 5, lane = threadIdx.x & 31;
    if (lane == 0) sh[w] = v;
    __syncthreads();
    if (w == 0) {
        float t = (lane < 8) ? sh[lane] : 0.f;
#pragma unroll
        for (int o = 4; o; o >>= 1) t += __shfl_xor_sync(0xffffffffu, t, o);
        if (lane == 0) sh[0] = t;
    }
    __syncthreads();
    float r = sh[0];
    __syncthreads();
    return r;
}

__global__ void add_ln(const float* __restrict__ xa, const float* __restrict__ xb,
                       const float* __restrict__ g, const float* __restrict__ bt,
                       float* __restrict__ out)
{
    __shared__ float sh[8];
    int row = blockIdx.x;
    int tid = threadIdx.x;          // 256 threads, 4 elems each
    size_t base = (size_t)row * D_;
    float4 v = reinterpret_cast<const float4*>(xa + base)[tid];
    float4 r = reinterpret_cast<const float4*>(xb + base)[tid];
    v.x += r.x; v.y += r.y; v.z += r.z; v.w += r.w;
    float s = v.x + v.y + v.z + v.w;
    float mean = block_sum_256(s, sh) * (1.0f / D_);
    float d0 = v.x - mean, d1 = v.y - mean, d2 = v.z - mean, d3 = v.w - mean;
    float sq = d0*d0 + d1*d1 + d2*d2 + d3*d3;
    float var = block_sum_256(sq, sh) * (1.0f / D_);
    float rs = rsqrtf(var + 1e-12f);
    float4 gg = reinterpret_cast<const float4*>(g)[tid];
    float4 bb = reinterpret_cast<const float4*>(bt)[tid];
    float4 o;
    o.x = d0 * rs * gg.x + bb.x;
    o.y = d1 * rs * gg.y + bb.y;
    o.z = d2 * rs * gg.z + bb.z;
    o.w = d3 * rs * gg.w + bb.w;
    reinterpret_cast<float4*>(out + base)[tid] = o;
}

// ---------------- orchestration ----------------
extern "C" void kernel_launch(void* const* d_in, const int* in_sizes, int n_in,
                              void* d_out, int out_size)
{
    (void)in_sizes; (void)n_in; (void)out_size;
    const float* x   = (const float*)d_in[0];
    const float* Wq  = (const float*)d_in[1];
    const float* Wk  = (const float*)d_in[2];
    const float* Wv  = (const float*)d_in[3];
    const float* E   = (const float*)d_in[4];
    const float* F   = (const float*)d_in[5];
    const float* g1  = (const float*)d_in[6];
    const float* bl1 = (const float*)d_in[7];
    const float* W1  = (const float*)d_in[8];
    const float* bb1 = (const float*)d_in[9];
    const float* W2  = (const float*)d_in[10];
    const float* bb2 = (const float*)d_in[11];
    const float* g2  = (const float*)d_in[12];
    const float* bl2 = (const float*)d_in[13];
    float* out = (float*)d_out;

    float* S = nullptr;
    cudaGetSymbolAddress((void**)&S, g_scratch);
    float* qb  = S + OFF_Q;
    float* kb  = S + OFF_K;
    float* vb  = S + OFF_V;
    float* kp  = S + OFF_KP;
    float* vp  = S + OFF_VP;
    float* sc  = S + OFF_SC;
    float* t1  = S + OFF_T1;
    float* yb  = S + OFF_Y;
    float* hb  = S + OFF_HB;
    float* xb  = S + OFF_XB;
    float* kpp = S + OFF_KPP;
    float* vpp = S + OFF_VPP;

    const long long NDll  = (long long)N_ * D_;
    const long long KPDll = (long long)KP_ * D_;
    const long long NKPll = (long long)N_ * KP_;

    for (int l = 0; l < LL_; l++) {
        const float* xin = (l == 0) ? x : xb;

        // --- Q, K, V projections: [8192,1024] x [1024,1024], NN ---
        dim3 gQ(D_/128, (B_*N_)/128, 1);
        gemm_tc<128,128,32,32,64,false,false,0><<<gQ,256>>>(
            xin, Wq + (size_t)l*D_*D_, qb, nullptr,
            B_*N_, D_, D_, D_, D_, D_, 0,0,0,0,0,0,0, 1, 1);
        gemm_tc<128,128,32,32,64,false,false,0><<<gQ,256>>>(
            xin, Wk + (size_t)l*D_*D_, kb, nullptr,
            B_*N_, D_, D_, D_, D_, D_, 0,0,0,0,0,0,0, 1, 1);
        gemm_tc<128,128,32,32,64,false,false,0><<<gQ,256>>>(
            xin, Wv + (size_t)l*D_*D_, vb, nullptr,
            B_*N_, D_, D_, D_, D_, D_, 0,0,0,0,0,0,0, 1, 1);

        // --- kp = E^T k, vp = F^T v : [256,1024], K=4096, TN, split-K=8 ---
        dim3 gP(D_/64, KP_/64, B_*SPLITK_);
        gemm_tc<64,64,32,32,32,true,false,0><<<gP,128>>>(
            E + (size_t)l*N_*KP_, kb, kpp, nullptr,
            KP_, D_, N_, KP_, D_, D_,
            0,0, 0,NDll, 0,KPDll, (long long)KPD_, 1, SPLITK_);
        gemm_tc<64,64,32,32,32,true,false,0><<<gP,128>>>(
            F + (size_t)l*N_*KP_, vb, vpp, nullptr,
            KP_, D_, N_, KP_, D_, D_,
            0,0, 0,NDll, 0,KPDll, (long long)KPD_, 1, SPLITK_);
        reduce_slices<<<KPD_/256,256>>>(kpp, kp, KPD_, SPLITK_, (long long)KPD_);
        reduce_slices<<<KPD_/256,256>>>(vpp, vp, KPD_, SPLITK_, (long long)KPD_);

        // --- scores[b,h] = Q_h Kp_h^T : [4096,256], K=64, NT, batched b*h ---
        dim3 gS(KP_/128, N_/128, B_*H_);
        gemm_tc<128,128,32,32,64,false,true,0><<<gS,256>>>(
            qb, kp, sc, nullptr,
            N_, KP_, HD_, D_, D_, KP_,
            HD_, NDll, HD_, KPDll, NKPll, (long long)H_*NKPll, 0, H_, 1);

        // --- softmax (in place, scale 1/8 folded in) ---
        softmax256<<<(B_*H_*N_)/8,256>>>(sc, B_*H_*N_);

        // --- attn = P Vp_h : [4096,64], K=256, NN, batched ---
        dim3 gA(HD_/64, N_/128, B_*H_);
        gemm_tc<128,64,32,32,32,false,false,0><<<gA,256>>>(
            sc, vp, t1, nullptr,
            N_, HD_, KP_, KP_, D_, D_,
            NKPll, (long long)H_*NKPll, HD_, KPDll, HD_, NDll, 0, H_, 1);

        // --- y = LN(attn + x) ---
        add_ln<<<B_*N_,256>>>(t1, xin, g1 + (size_t)l*D_, bl1 + (size_t)l*D_, yb);

        // --- h = gelu(y W1^T + b1) : [8192,4096], K=1024, NT ---
        dim3 gF1(FF_/128, (B_*N_)/128, 1);
        gemm_tc<128,128,32,32,64,false,true,2><<<gF1,256>>>(
            yb, W1 + (size_t)l*FF_*D_, hb, bb1 + (size_t)l*FF_,
            B_*N_, FF_, D_, D_, D_, FF_, 0,0,0,0,0,0,0, 1, 1);

        // --- o = h W2^T + b2 : [8192,1024], K=4096, NT ---
        dim3 gF2(D_/128, (B_*N_)/128, 1);
        gemm_tc<128,128,32,32,64,false,true,1><<<gF2,256>>>(
            hb, W2 + (size_t)l*D_*FF_, t1, bb2 + (size_t)l*D_,
            B_*N_, D_, FF_, FF_, FF_, D_, 0,0,0,0,0,0,0, 1, 1);

        // --- x_next = LN(o + y) ---
        add_ln<<<B_*N_,256>>>(t1, yb, g2 + (size_t)l*D_, bl2 + (size_t)l*D_,
                              (l == LL_-1) ? out : xb);
    }
}